// round 15
// baseline (speedup 1.0000x reference)
#include <cuda_runtime.h>
#include <math.h>

#define B_   16
#define T_   128
#define I_   256
#define H_   256
#define NZ_  1024          // 4*H
#define NBLK 128           // rec blocks: 4 groups x 32
#define GRPB 32            // rec arrivals per (group,step)
#define XPROD 20           // persistent xz producer blocks (SMs 128..147)
#define NTILE (T_ * 8)     // 1024 (t, n0) tiles, t-major
#define XARR  (8 * 256)    // xz arrivals per t: 8 n-tiles x 256 threads

typedef unsigned long long ull;

// Scratch (static device globals: no allocation)
__device__ float    g_xz[T_ * NZ_ * B_];   // [t][n][b]  8 MB
__device__ float    g_h[2][B_ * H_];       // ping-pong hidden state [b][u]
__device__ unsigned g_grp[4 * T_ * 8];     // per-(group,step) counters, 32B apart
__device__ unsigned g_xzc[T_ * 8];         // per-t xz-ready counters, 32B apart

// fast transcendentals: ex2.approx + rcp.approx (~1e-6 rel err each)
__device__ __forceinline__ float fsigmoid(float x) {
    float e; asm("ex2.approx.ftz.f32 %0, %1;" : "=f"(e) : "f"(-1.4426950408889634f * x));
    float r; asm("rcp.approx.ftz.f32 %0, %1;" : "=f"(r) : "f"(1.0f + e));
    return r;
}
__device__ __forceinline__ float ftanh_(float x) {
    x = fminf(fmaxf(x, -30.0f), 30.0f);
    float e; asm("ex2.approx.ftz.f32 %0, %1;" : "=f"(e) : "f"(2.8853900817779268f * x));
    float r; asm("rcp.approx.ftz.f32 %0, %1;" : "=f"(r) : "f"(e + 1.0f));
    return (e - 1.0f) * r;
}

// packed f32x2 helpers (sm_100+)
__device__ __forceinline__ ull pack2(float lo, float hi) {
    ull r; asm("mov.b64 %0, {%1,%2};" : "=l"(r) : "f"(lo), "f"(hi)); return r;
}
__device__ __forceinline__ void unpack2(ull v, float& lo, float& hi) {
    asm("mov.b64 {%0,%1}, %2;" : "=f"(lo), "=f"(hi) : "l"(v));
}
__device__ __forceinline__ ull fma2(ull a, ull b, ull c) {
    ull d; asm("fma.rn.f32x2 %0, %1, %2, %3;" : "=l"(d) : "l"(a), "l"(b), "l"(c));
    return d;
}
__device__ __forceinline__ unsigned acq_load(const unsigned* p) {
    unsigned v;
    asm volatile("ld.acquire.gpu.global.u32 %0, [%1];" : "=r"(v) : "l"(p) : "memory");
    return v;
}
__device__ __forceinline__ void rel_red(unsigned* p) {
    asm volatile("red.release.gpu.global.add.u32 [%0], %1;" :: "l"(p), "r"(1u) : "memory");
}

// ---------------------------------------------------------------------------
// reset kernel: zero all counters (graph-replay safe, runs before fused)
// ---------------------------------------------------------------------------
__global__ void __launch_bounds__(256)
reset_kernel()
{
    for (int i = threadIdx.x; i < 4 * T_ * 8; i += 256) g_grp[i] = 0u;
    for (int i = threadIdx.x; i < T_ * 8; i += 256)     g_xzc[i] = 0u;
}

// ---------------------------------------------------------------------------
// xz producer: 20 persistent blocks sweep 1024 (t, n0) tiles t-major.
// Tile g: t = g>>3, n0 = (g&7)*128. XZ[t][n][b] = sum_k x[b][t][k]*Wih[k][n].
// Streams x in 1KB k-panels (16k x 16b) + 8KB w panels -> small smem.
// Producer rate ~0.5us/t >> consumer 2.6us/t: rec stalls only at t~0.
// ---------------------------------------------------------------------------
__device__ void xz_part(const float* __restrict__ x,
                        const float* __restrict__ Wih, int pid)
{
    __shared__ float xp_s[16 * 16];     // [k'][b], 1 KB
    __shared__ float wp_s[16 * 128];    // 8 KB

    const int tid = threadIdx.x;
    const int bq  = tid >> 6;           // 0..3 -> b0 = 4*bq
    const int ng  = tid & 63;           // 0..63 -> 2 n-cols
    const int b0  = bq * 4;

    for (int g = pid; g < NTILE; g += XPROD) {
        const int t  = g >> 3;
        const int n0 = (g & 7) * 128;

        float acc[4][2];
        #pragma unroll
        for (int i = 0; i < 4; i++) { acc[i][0] = 0.f; acc[i][1] = 0.f; }

        for (int kb = 0; kb < 16; kb++) {
            __syncthreads();   // xp_s/wp_s reuse guard
            {   // stage x panel: k' = tid&15, b = tid>>4 (coalesced over k)
                int kk = tid & 15, b = tid >> 4;
                xp_s[kk * 16 + b] = x[((size_t)b * T_ + t) * I_ + kb * 16 + kk];
                // stage w panel: 512 float4, 256 threads x 2
                int q0 = tid, q1 = tid + 256;
                ((float4*)wp_s)[q0] =
                    ((const float4*)(Wih + (size_t)(kb * 16 + (q0 >> 5)) * NZ_ + n0))[q0 & 31];
                ((float4*)wp_s)[q1] =
                    ((const float4*)(Wih + (size_t)(kb * 16 + (q1 >> 5)) * NZ_ + n0))[q1 & 31];
            }
            __syncthreads();
            #pragma unroll
            for (int kk = 0; kk < 16; kk++) {
                float x0 = xp_s[kk * 16 + b0 + 0];
                float x1 = xp_s[kk * 16 + b0 + 1];
                float x2 = xp_s[kk * 16 + b0 + 2];
                float x3 = xp_s[kk * 16 + b0 + 3];
                float w0 = wp_s[kk * 128 + ng * 2 + 0];
                float w1 = wp_s[kk * 128 + ng * 2 + 1];
                acc[0][0] += x0 * w0;  acc[0][1] += x0 * w1;
                acc[1][0] += x1 * w0;  acc[1][1] += x1 * w1;
                acc[2][0] += x2 * w0;  acc[2][1] += x2 * w1;
                acc[3][0] += x3 * w0;  acc[3][1] += x3 * w1;
            }
        }

        #pragma unroll
        for (int j = 0; j < 2; j++) {
            float4 o = make_float4(acc[0][j], acc[1][j], acc[2][j], acc[3][j]);
            *(float4*)&g_xz[(size_t)(t * NZ_ + n0 + ng * 2 + j) * B_ + b0] = o;
        }
        // per-thread release: orders THIS thread's xz stores; 2048 arrivals/t
        rel_red(&g_xzc[t * 8]);
    }
}

// ---------------------------------------------------------------------------
// rec part: EXACT round-10 structure (best proven: 329 us rec), 4 groups x
// 32 blocks, warp = unit, d_s + warp0 epilogue, tid0 red per block.
// Delta vs round-10: tid0 also polls the xz-ready counter (back-to-back
// with the group poll -> overlapped L2 round trips).
// ---------------------------------------------------------------------------
__device__ void rec_part(const float* __restrict__ h_init,
                         const float* __restrict__ c_init,
                         const float* __restrict__ out0,
                         const float* __restrict__ Wih,
                         const float* __restrict__ Whh,
                         const float* __restrict__ b_ih,
                         const float* __restrict__ b_hh,
                         float* __restrict__ dout)
{
    __shared__ float h_s[4 * H_];           // 4 KB: the group's 4 batches
    __shared__ float d_s[8][2][4][4];       // [unit][mat][gate][batch]
    __shared__ float A_s[8][4][4];          // running atten@Wa
    __shared__ float c_s[8][4];
    __shared__ float att_s[8][4];
    __shared__ float bias_s[8][4];

    const int tid  = threadIdx.x;
    const int bid  = blockIdx.x;
    const int g    = bid >> 5;     // group 0..3 -> batches 4g..4g+3
    const int r    = bid & 31;     // unit block -> units 8r..8r+7
    const int u0   = r * 8;
    const int b0   = g * 4;
    const int w    = tid >> 5;     // warp = local unit lu (0..7)
    const int lane = tid & 31;
    const int cs   = lane >> 4;    // 0 -> Whh, 1 -> Wa (Wih rows 256..511)
    const int kc   = lane & 15;    // k-pair base = 32*j + 2*kc

    // packed weight slice in registers: wr2[c][j] = {W[k0][n], W[k0+1][n]}
    ull wr2[4][8];
    #pragma unroll
    for (int c = 0; c < 4; c++) {
        const int n = u0 + w + 256 * c;
        #pragma unroll
        for (int j = 0; j < 8; j++) {
            const int k0 = 32 * j + 2 * kc;
            float w0 = cs ? Wih[(size_t)(256 + k0) * NZ_ + n]
                          : Whh[(size_t)k0 * NZ_ + n];
            float w1 = cs ? Wih[(size_t)(256 + k0 + 1) * NZ_ + n]
                          : Whh[(size_t)(k0 + 1) * NZ_ + n];
            wr2[c][j] = pack2(w0, w1);
        }
    }

    if (tid < 32) {
        int lu = tid >> 2, c = tid & 3;          // bias per (unit, gate)
        bias_s[lu][c] = b_ih[u0 + lu + 256 * c] + b_hh[u0 + lu + 256 * c];
    }
    if (tid < 32) {
        int lu = tid >> 2, bl = tid & 3;
        int b = b0 + bl, u = u0 + lu;
        c_s[lu][bl]   = c_init[b * H_ + u];
        att_s[lu][bl] = out0[b * H_ + u];        // atten includes buf[0] = out0
    }

    auto do_gemm = [&]() {
        ull acc2[4][4];                          // [batch][gate]
        #pragma unroll
        for (int i = 0; i < 4; i++)
            #pragma unroll
            for (int c = 0; c < 4; c++) acc2[i][c] = pack2(0.f, 0.f);
        #pragma unroll
        for (int j = 0; j < 8; j++) {
            const int k0 = 32 * j + 2 * kc;
            ull h0 = *(const ull*)&h_s[0 * H_ + k0];
            ull h1 = *(const ull*)&h_s[1 * H_ + k0];
            ull h2 = *(const ull*)&h_s[2 * H_ + k0];
            ull h3 = *(const ull*)&h_s[3 * H_ + k0];
            #pragma unroll
            for (int c = 0; c < 4; c++) {
                ull wv = wr2[c][j];
                acc2[0][c] = fma2(h0, wv, acc2[0][c]);
                acc2[1][c] = fma2(h1, wv, acc2[1][c]);
                acc2[2][c] = fma2(h2, wv, acc2[2][c]);
                acc2[3][c] = fma2(h3, wv, acc2[3][c]);
            }
        }
        float acc[4][4];
        #pragma unroll
        for (int i = 0; i < 4; i++)
            #pragma unroll
            for (int c = 0; c < 4; c++) {
                float lo, hi; unpack2(acc2[i][c], lo, hi);
                acc[i][c] = lo + hi;
            }
        // butterfly-allreduce over the 16 kc lanes (stays within cs halves)
        #pragma unroll
        for (int off = 8; off >= 1; off >>= 1)
            #pragma unroll
            for (int i = 0; i < 4; i++)
                #pragma unroll
                for (int c = 0; c < 4; c++)
                    acc[i][c] += __shfl_xor_sync(0xffffffffu, acc[i][c], off);
        if (kc == 0) {
            #pragma unroll
            for (int i = 0; i < 4; i++)
                #pragma unroll
                for (int c = 0; c < 4; c++)
                    d_s[w][cs][c][i] = acc[i][c];
        }
    };

    // ---- prestep: A_0 = out0 @ Wa  (out0 excluded from h recurrence) ----
    *(float4*)&h_s[tid * 4] = *(const float4*)&out0[b0 * H_ + tid * 4];
    __syncthreads();
    do_gemm();
    __syncthreads();
    if (tid < 32) {
        int lu = tid >> 2, bl = tid & 3;
        #pragma unroll
        for (int c = 0; c < 4; c++) A_s[lu][c][bl] = d_s[lu][1][c][bl];
    }

    // ---- main sequential loop (round-10 skeleton) ----
    for (int t = 0; t < T_; t++) {
        // wait: xz[t] produced AND (t>0) all 32 group blocks finished t-1.
        if (tid == 0) {
            const unsigned* xc = &g_xzc[t * 8];
            const unsigned* gc = &g_grp[(g * T_ + (t - 1)) * 8];
            unsigned vx = acq_load(xc);
            unsigned vg = (t > 0) ? acq_load(gc) : GRPB;
            while (vx < XARR) vx = acq_load(xc);
            while (vg < GRPB) vg = acq_load(gc);
        }
        __syncthreads();   // (A) release + h_s/d_s reuse guard

        // prefetch this step's xz (ordered after acquire via the bar)
        float xzv[4];
        const int lu = (tid & 31) >> 2;
        const int bl = tid & 3;
        if (tid < 32) {
            #pragma unroll
            for (int c = 0; c < 4; c++)
                xzv[c] = __ldcg(&g_xz[(size_t)(t * NZ_ + (u0 + lu) + 256 * c) * B_ + (b0 + bl)]);
        }

        // stage h_{t-1} for the group's 4 batches: one float4 per thread
        {
            const float* hsrc = (t == 0) ? (h_init + b0 * H_)
                                         : (&g_h[(t - 1) & 1][b0 * H_]);
            float4 v = __ldcg((const float4*)(hsrc + tid * 4));
            *(float4*)&h_s[tid * 4] = v;
        }
        __syncthreads();   // (B)

        do_gemm();
        __syncthreads();   // (C)

        if (tid < 32) {
            const int u = u0 + lu;
            const int b = b0 + bl;
            float z[4];
            #pragma unroll
            for (int c = 0; c < 4; c++) {
                float Av = A_s[lu][c][bl];
                if (t > 0) Av += d_s[lu][1][c][bl];  // A_t = A_{t-1} + h_{t-1}@Wa
                A_s[lu][c][bl] = Av;
                z[c] = xzv[c] + Av + d_s[lu][0][c][bl] + bias_s[lu][c];
            }
            float si = fsigmoid(z[0]);
            float sf = fsigmoid(z[1]);
            float tg = ftanh_(z[2]);
            float so = fsigmoid(z[3]);
            float cn = sf * c_s[lu][bl] + si * tg;
            float hn = so * ftanh_(cn);
            // publish + release FIRST (critical path), bookkeeping after
            if (t < T_ - 1) {
                __stcg(&g_h[t & 1][b * H_ + u], hn);
                __syncwarp();
                if (tid == 0) rel_red(&g_grp[(g * T_ + t) * 8]);
            }
            c_s[lu][bl] = cn;
            if (t < T_ - 1) att_s[lu][bl] += hn;     // attens[-1] sums t<=T-2
            if (t == T_ - 2) {
                dout[3 * 4096 + b * H_ + u] = hn;    // h_prevs[-1]
                dout[4 * 4096 + b * H_ + u] = cn;    // c_prevs[-1]
            }
            if (t == T_ - 1) {
                dout[0 * 4096 + b * H_ + u] = hn;    // out_f (B,1,H)
                dout[1 * 4096 + b * H_ + u] = hn;    // h_f   (1,B,H)
                dout[2 * 4096 + b * H_ + u] = cn;    // c_f   (1,B,H)
            }
        }
    }

    if (tid < 32) {
        int lu2 = tid >> 2, bl2 = tid & 3;
        dout[5 * 4096 + (b0 + bl2) * H_ + (u0 + lu2)] = att_s[lu2][bl2];
    }
}

// ---------------------------------------------------------------------------
// fused kernel: grid = 148 = #SMs (wave-1 guaranteed, 1 block/SM).
// bids [0,128) = recurrence, [128,148) = persistent xz producers.
// ---------------------------------------------------------------------------
__global__ void __launch_bounds__(256)
fused_kernel(const float* __restrict__ h_init, const float* __restrict__ c_init,
             const float* __restrict__ out0,  const float* __restrict__ x,
             const float* __restrict__ Wih,   const float* __restrict__ Whh,
             const float* __restrict__ b_ih,  const float* __restrict__ b_hh,
             float* __restrict__ dout)
{
    if (blockIdx.x >= NBLK) {
        xz_part(x, Wih, blockIdx.x - NBLK);
        return;
    }
    rec_part(h_init, c_init, out0, Wih, Whh, b_ih, b_hh, dout);
}

// ---------------------------------------------------------------------------
// inputs (metadata order): x, hidden_state, cell_state, out, Wih, Whh,
// b_ih, b_hh, W1, b1, W2, b2, W3, b3, bsize, time_step
// W1..b3 are dead (softmax over singleton axis makes weights == 1).
// ---------------------------------------------------------------------------
extern "C" void kernel_launch(void* const* d_in, const int* in_sizes, int n_in,
                              void* d_out, int out_size)
{
    const float* x       = (const float*)d_in[0];
    const float* h_init  = (const float*)d_in[1];
    const float* c_init  = (const float*)d_in[2];
    const float* out0    = (const float*)d_in[3];
    const float* Wih     = (const float*)d_in[4];
    const float* Whh     = (const float*)d_in[5];
    const float* b_ih    = (const float*)d_in[6];
    const float* b_hh    = (const float*)d_in[7];
    float* dout = (float*)d_out;

    reset_kernel<<<1, 256>>>();
    fused_kernel<<<NBLK + XPROD, 256>>>(h_init, c_init, out0, x,
                                        Wih, Whh, b_ih, b_hh, dout);
}

// round 16
// speedup vs baseline: 1.3937x; 1.3937x over previous
#include <cuda_runtime.h>
#include <math.h>

#define B_   16
#define T_   128
#define I_   256
#define H_   256
#define NZ_  1024          // 4*H
#define NBLK 128           // rec blocks: 4 groups x 32
#define GRPB 32            // rec arrivals per (group,step)

typedef unsigned long long ull;

// Scratch (static device globals: no allocation)
__device__ float    g_xz[T_ * NZ_ * B_];   // [t][n][b]  8 MB
__device__ float    g_h[2][B_ * H_];       // ping-pong hidden state [b][u]
__device__ unsigned g_arr[4 * T_ * 8];     // per-(group,step) counters, 32B apart

// fast transcendentals: ex2.approx + rcp.approx (~1e-6 rel err each)
__device__ __forceinline__ float fsigmoid(float x) {
    float e; asm("ex2.approx.ftz.f32 %0, %1;" : "=f"(e) : "f"(-1.4426950408889634f * x));
    float r; asm("rcp.approx.ftz.f32 %0, %1;" : "=f"(r) : "f"(1.0f + e));
    return r;
}
__device__ __forceinline__ float ftanh_(float x) {
    x = fminf(fmaxf(x, -30.0f), 30.0f);
    float e; asm("ex2.approx.ftz.f32 %0, %1;" : "=f"(e) : "f"(2.8853900817779268f * x));
    float r; asm("rcp.approx.ftz.f32 %0, %1;" : "=f"(r) : "f"(e + 1.0f));
    return (e - 1.0f) * r;
}

// packed f32x2 helpers (sm_100+)
__device__ __forceinline__ ull pack2(float lo, float hi) {
    ull r; asm("mov.b64 %0, {%1,%2};" : "=l"(r) : "f"(lo), "f"(hi)); return r;
}
__device__ __forceinline__ void unpack2(ull v, float& lo, float& hi) {
    asm("mov.b64 {%0,%1}, %2;" : "=f"(lo), "=f"(hi) : "l"(v));
}
__device__ __forceinline__ ull fma2(ull a, ull b, ull c) {
    ull d; asm("fma.rn.f32x2 %0, %1, %2, %3;" : "=l"(d) : "l"(a), "l"(b), "l"(c));
    return d;
}

// ---------------------------------------------------------------------------
// Kernel 1: XZ[t][n][b] = sum_k x[b][t][k] * Wih[k][n]   (k < 256 rows of Wih)
// grid (8 n-blocks, 64 t-pairs), 256 threads: each block computes TWO
// timesteps sharing each staged W panel (halves W L2 traffic vs 1-t blocks).
// Proven correct as the xz path of round 13. Also resets the rec counters
// (graph-replay safe: stream-ordered before rec_kernel).
// ---------------------------------------------------------------------------
__global__ void __launch_bounds__(256)
xz_kernel(const float* __restrict__ x, const float* __restrict__ Wih)
{
    if (blockIdx.y == 0) {
        // 8 blocks x 256 threads zero 4096 counters (2 each)
        int base = (blockIdx.x * 256 + threadIdx.x) * 2;
        g_arr[base] = 0u;
        g_arr[base + 1] = 0u;
    }

    __shared__ float x_s[2][I_ * B_];   // [half][k][b], 32 KB
    __shared__ float w_s[16 * 128];     // shared 16-row k-panel, 8 KB

    const int tid  = threadIdx.x;
    const int half = tid >> 7;          // 0/1 -> t0/t1
    const int htid = tid & 127;
    const int n0   = blockIdx.x * 128;
    const int t    = blockIdx.y * 2 + half;

    // stage x[:, t, :] transposed -> x_s[half][k][b]
    for (int idx = htid; idx < B_ * I_; idx += 128) {
        int b = idx >> 8;
        int k = idx & 255;
        x_s[half][k * B_ + b] = x[(b * T_ + t) * I_ + k];
    }

    const int bq = htid >> 5;       // 0..3  -> b tile of 4
    const int ng = htid & 31;       // 0..31 -> n tile of 4
    const int b0 = bq * 4;
    const int nn = ng * 4;

    float acc[4][4];
    #pragma unroll
    for (int i = 0; i < 4; i++)
        #pragma unroll
        for (int j = 0; j < 4; j++) acc[i][j] = 0.f;

    for (int kb = 0; kb < 16; kb++) {
        __syncthreads();   // protects x_s fill (1st iter) and w_s reuse
        for (int q = tid; q < 512; q += 256) {      // all 256 threads stage w_s
            int r  = q >> 5;
            int c4 = q & 31;
            ((float4*)w_s)[q] =
                ((const float4*)(Wih + (size_t)(kb * 16 + r) * NZ_ + n0))[c4];
        }
        __syncthreads();
        #pragma unroll
        for (int kk = 0; kk < 16; kk++) {
            float4 xv = *(const float4*)&x_s[half][(kb * 16 + kk) * B_ + b0];
            float4 wv = *(const float4*)&w_s[kk * 128 + nn];
            float xr[4] = {xv.x, xv.y, xv.z, xv.w};
            float wr_[4] = {wv.x, wv.y, wv.z, wv.w};
            #pragma unroll
            for (int i = 0; i < 4; i++)
                #pragma unroll
                for (int j = 0; j < 4; j++)
                    acc[i][j] += xr[i] * wr_[j];
        }
    }

    #pragma unroll
    for (int j = 0; j < 4; j++) {
        float4 o = make_float4(acc[0][j], acc[1][j], acc[2][j], acc[3][j]);
        *(float4*)&g_xz[(size_t)(t * NZ_ + n0 + nn + j) * B_ + b0] = o;
    }
}

// ---------------------------------------------------------------------------
// Kernel 2: persistent recurrence — EXACT round-10 structure (best proven:
// 329 us). 4 independent groups of 32 blocks (group g owns batches 4g..4g+3;
// block r owns units 8r..8r+7, warp = unit). Per-group acquire/release
// counter, d_s + warp0 epilogue.
// ---------------------------------------------------------------------------
__global__ void __launch_bounds__(256)
rec_kernel(const float* __restrict__ h_init, const float* __restrict__ c_init,
           const float* __restrict__ out0,
           const float* __restrict__ Wih,  const float* __restrict__ Whh,
           const float* __restrict__ b_ih, const float* __restrict__ b_hh,
           float* __restrict__ dout)
{
    __shared__ float h_s[4 * H_];           // 4 KB: the group's 4 batches
    __shared__ float d_s[8][2][4][4];       // [unit][mat][gate][batch]
    __shared__ float A_s[8][4][4];          // running atten@Wa
    __shared__ float c_s[8][4];
    __shared__ float att_s[8][4];
    __shared__ float bias_s[8][4];

    const int tid  = threadIdx.x;
    const int bid  = blockIdx.x;
    const int g    = bid >> 5;     // group 0..3 -> batches 4g..4g+3
    const int r    = bid & 31;     // unit block -> units 8r..8r+7
    const int u0   = r * 8;
    const int b0   = g * 4;
    const int w    = tid >> 5;     // warp = local unit lu (0..7)
    const int lane = tid & 31;
    const int cs   = lane >> 4;    // 0 -> Whh, 1 -> Wa (Wih rows 256..511)
    const int kc   = lane & 15;    // k-pair base = 32*j + 2*kc

    // packed weight slice in registers: wr2[c][j] = {W[k0][n], W[k0+1][n]}
    ull wr2[4][8];
    #pragma unroll
    for (int c = 0; c < 4; c++) {
        const int n = u0 + w + 256 * c;
        #pragma unroll
        for (int j = 0; j < 8; j++) {
            const int k0 = 32 * j + 2 * kc;
            float w0 = cs ? Wih[(size_t)(256 + k0) * NZ_ + n]
                          : Whh[(size_t)k0 * NZ_ + n];
            float w1 = cs ? Wih[(size_t)(256 + k0 + 1) * NZ_ + n]
                          : Whh[(size_t)(k0 + 1) * NZ_ + n];
            wr2[c][j] = pack2(w0, w1);
        }
    }

    if (tid < 32) {
        int lu = tid >> 2, c = tid & 3;          // bias per (unit, gate)
        bias_s[lu][c] = b_ih[u0 + lu + 256 * c] + b_hh[u0 + lu + 256 * c];
    }
    if (tid < 32) {
        int lu = tid >> 2, bl = tid & 3;
        int b = b0 + bl, u = u0 + lu;
        c_s[lu][bl]   = c_init[b * H_ + u];
        att_s[lu][bl] = out0[b * H_ + u];        // atten includes buf[0] = out0
    }

    auto do_gemm = [&]() {
        ull acc2[4][4];                          // [batch][gate]
        #pragma unroll
        for (int i = 0; i < 4; i++)
            #pragma unroll
            for (int c = 0; c < 4; c++) acc2[i][c] = pack2(0.f, 0.f);
        #pragma unroll
        for (int j = 0; j < 8; j++) {
            const int k0 = 32 * j + 2 * kc;
            ull h0 = *(const ull*)&h_s[0 * H_ + k0];
            ull h1 = *(const ull*)&h_s[1 * H_ + k0];
            ull h2 = *(const ull*)&h_s[2 * H_ + k0];
            ull h3 = *(const ull*)&h_s[3 * H_ + k0];
            #pragma unroll
            for (int c = 0; c < 4; c++) {
                ull wv = wr2[c][j];
                acc2[0][c] = fma2(h0, wv, acc2[0][c]);
                acc2[1][c] = fma2(h1, wv, acc2[1][c]);
                acc2[2][c] = fma2(h2, wv, acc2[2][c]);
                acc2[3][c] = fma2(h3, wv, acc2[3][c]);
            }
        }
        float acc[4][4];
        #pragma unroll
        for (int i = 0; i < 4; i++)
            #pragma unroll
            for (int c = 0; c < 4; c++) {
                float lo, hi; unpack2(acc2[i][c], lo, hi);
                acc[i][c] = lo + hi;
            }
        // butterfly-allreduce over the 16 kc lanes (stays within cs halves)
        #pragma unroll
        for (int off = 8; off >= 1; off >>= 1)
            #pragma unroll
            for (int i = 0; i < 4; i++)
                #pragma unroll
                for (int c = 0; c < 4; c++)
                    acc[i][c] += __shfl_xor_sync(0xffffffffu, acc[i][c], off);
        if (kc == 0) {
            #pragma unroll
            for (int i = 0; i < 4; i++)
                #pragma unroll
                for (int c = 0; c < 4; c++)
                    d_s[w][cs][c][i] = acc[i][c];
        }
    };

    // ---- prestep: A_0 = out0 @ Wa  (out0 excluded from h recurrence) ----
    *(float4*)&h_s[tid * 4] = *(const float4*)&out0[b0 * H_ + tid * 4];
    __syncthreads();
    do_gemm();
    __syncthreads();
    if (tid < 32) {
        int lu = tid >> 2, bl = tid & 3;
        #pragma unroll
        for (int c = 0; c < 4; c++) A_s[lu][c][bl] = d_s[lu][1][c][bl];
    }

    // ---- main sequential loop (round-10 skeleton) ----
    for (int t = 0; t < T_; t++) {
        // warp 0 prefetches this step's xz early (overlaps the wait)
        float xzv[4];
        const int lu = (tid & 31) >> 2;
        const int bl = tid & 3;
        if (tid < 32) {
            #pragma unroll
            for (int c = 0; c < 4; c++)
                xzv[c] = __ldcg(&g_xz[(size_t)(t * NZ_ + (u0 + lu) + 256 * c) * B_ + (b0 + bl)]);
        }

        // wait: all 32 blocks of this group finished step t-1
        if (t > 0 && tid == 0) {
            const unsigned* ctr = &g_arr[(g * T_ + (t - 1)) * 8];
            unsigned v;
            do {
                asm volatile("ld.acquire.gpu.global.u32 %0, [%1];"
                             : "=r"(v) : "l"(ctr) : "memory");
            } while (v < GRPB);
        }
        __syncthreads();   // (A) release + h_s/d_s reuse guard

        // stage h_{t-1} for the group's 4 batches: one float4 per thread
        {
            const float* hsrc = (t == 0) ? (h_init + b0 * H_)
                                         : (&g_h[(t - 1) & 1][b0 * H_]);
            float4 v = __ldcg((const float4*)(hsrc + tid * 4));
            *(float4*)&h_s[tid * 4] = v;
        }
        __syncthreads();   // (B)

        do_gemm();
        __syncthreads();   // (C)

        if (tid < 32) {
            const int u = u0 + lu;
            const int b = b0 + bl;
            float z[4];
            #pragma unroll
            for (int c = 0; c < 4; c++) {
                float Av = A_s[lu][c][bl];
                if (t > 0) Av += d_s[lu][1][c][bl];  // A_t = A_{t-1} + h_{t-1}@Wa
                A_s[lu][c][bl] = Av;
                z[c] = xzv[c] + Av + d_s[lu][0][c][bl] + bias_s[lu][c];
            }
            float si = fsigmoid(z[0]);
            float sf = fsigmoid(z[1]);
            float tg = ftanh_(z[2]);
            float so = fsigmoid(z[3]);
            float cn = sf * c_s[lu][bl] + si * tg;
            float hn = so * ftanh_(cn);
            // publish + release FIRST (critical path), bookkeeping after
            if (t < T_ - 1) {
                __stcg(&g_h[t & 1][b * H_ + u], hn);
                __syncwarp();
                if (tid == 0) {
                    asm volatile("red.release.gpu.global.add.u32 [%0], %1;"
                                 :: "l"(&g_arr[(g * T_ + t) * 8]), "r"(1u)
                                 : "memory");
                }
            }
            c_s[lu][bl] = cn;
            if (t < T_ - 1) att_s[lu][bl] += hn;     // attens[-1] sums t<=T-2
            if (t == T_ - 2) {
                dout[3 * 4096 + b * H_ + u] = hn;    // h_prevs[-1]
                dout[4 * 4096 + b * H_ + u] = cn;    // c_prevs[-1]
            }
            if (t == T_ - 1) {
                dout[0 * 4096 + b * H_ + u] = hn;    // out_f (B,1,H)
                dout[1 * 4096 + b * H_ + u] = hn;    // h_f   (1,B,H)
                dout[2 * 4096 + b * H_ + u] = cn;    // c_f   (1,B,H)
            }
        }
    }

    if (tid < 32) {
        int lu2 = tid >> 2, bl2 = tid & 3;
        dout[5 * 4096 + (b0 + bl2) * H_ + (u0 + lu2)] = att_s[lu2][bl2];
    }
}

// ---------------------------------------------------------------------------
// inputs (metadata order): x, hidden_state, cell_state, out, Wih, Whh,
// b_ih, b_hh, W1, b1, W2, b2, W3, b3, bsize, time_step
// W1..b3 are dead (softmax over singleton axis makes weights == 1).
// ---------------------------------------------------------------------------
extern "C" void kernel_launch(void* const* d_in, const int* in_sizes, int n_in,
                              void* d_out, int out_size)
{
    const float* x       = (const float*)d_in[0];
    const float* h_init  = (const float*)d_in[1];
    const float* c_init  = (const float*)d_in[2];
    const float* out0    = (const float*)d_in[3];
    const float* Wih     = (const float*)d_in[4];
    const float* Whh     = (const float*)d_in[5];
    const float* b_ih    = (const float*)d_in[6];
    const float* b_hh    = (const float*)d_in[7];
    float* dout = (float*)d_out;

    dim3 g1(8, T_ / 2);
    xz_kernel<<<g1, 256>>>(x, Wih);
    rec_kernel<<<NBLK, 256>>>(h_init, c_init, out0, Wih, Whh, b_ih, b_hh, dout);
}